// round 15
// baseline (speedup 1.0000x reference)
#include <cuda_runtime.h>
#include <cuda_bf16.h>

#define A_N      4096
#define N_OBJ    8192
#define IN_DIM   16
#define EMBED    128
#define MAX_OBJ  16
#define DEG      8
#define OBS_DEG  8
#define POS_DIM  2
#define ORIG     18          // IN_DIM + POS_DIM
#define ORIG_P   20          // padded row stride (80B, 16B aligned)
#define OUTC     288         // MAX_OBJ * ORIG
#define NLOG     17          // MAX_OBJ + 1
#define KTOT     128         // DEG * MAX_OBJ
#define THRES    0.02f
#define THRES2   (THRES * THRES)

typedef unsigned long long ull;

__device__ __forceinline__ ull f2fma(ull a, ull b, ull c) {
    ull d;
    asm("fma.rn.f32x2 %0, %1, %2, %3;" : "=l"(d) : "l"(a), "l"(b), "l"(c));
    return d;
}
__device__ __forceinline__ float f2sum(ull v) {
    float lo, hi;
    asm("mov.b64 {%0, %1}, %2;" : "=f"(lo), "=f"(hi) : "l"(v));
    return lo + hi;
}
__device__ __forceinline__ ull f2pack(float lo, float hi) {
    ull v;
    asm("mov.b64 %0, {%1, %2};" : "=l"(v) : "f"(lo), "f"(hi));
    return v;
}

// ---------------- device scratch ----------------
__device__ float  g_enc[A_N * EMBED];
__device__ float  g_elems0[A_N * OUTC];
__device__ int    g_npred[A_N];
__device__ float  g_Spre[A_N * EMBED];
// k-quad interleaved: Q[kq*cols + c] = {W[4kq][c], ..., W[4kq+3][c]}
__device__ float4 g_mdec_WxQ[32 * OUTC];
__device__ float4 g_mdec_WsQ[32 * NLOG];
// FOLDED dec weights: WxF = menc_W2 @ dec_Wx, WsF = menc_W2 @ dec_Ws
__device__ float4 g_decF_WxQ[32 * OUTC];
__device__ float4 g_decF_WsQ[32 * NLOG];
__device__ float  g_bxF[OUTC];
__device__ float  g_bsF[NLOG];

#define PREP_TOTAL (32 * OUTC + 32 * NLOG)
#define PREP_BLOCKS ((PREP_TOTAL + 127) / 128)
#define FOLD_BLOCKS (OUTC + NLOG)
#define ENC_BLOCKS (A_N / 4)

__device__ __forceinline__ float4 quad(const float* __restrict__ W, int cols, int kq, int c) {
    return make_float4(W[(4 * kq    ) * cols + c], W[(4 * kq + 1) * cols + c],
                       W[(4 * kq + 2) * cols + c], W[(4 * kq + 3) * cols + c]);
}

// ---------------------------------------------------------------------------
// K1 (fused, 128 thr): blocks [0,1024) = obs encode (raw enc_W2 — reads NO
// prep outputs); [1024,+PREP) = mdec quad prep; rest = dec weight fold.
// ---------------------------------------------------------------------------
__global__ __launch_bounds__(128) void pre_kernel(
    const float* __restrict__ obj_x, const float* __restrict__ obj_pos,
    const float* __restrict__ agent_pos,
    const float* __restrict__ W1, const float* __restrict__ b1,
    const float* __restrict__ eW2, const float* __restrict__ b2,
    const int*   __restrict__ obs_src,
    const float* __restrict__ mWx, const float* __restrict__ mWs,
    const float* __restrict__ mencW2, const float* __restrict__ mencb2,
    const float* __restrict__ decWx, const float* __restrict__ decbx,
    const float* __restrict__ decWs, const float* __restrict__ decbs)
{
    const int t = threadIdx.x;

    if (blockIdx.x >= ENC_BLOCKS && blockIdx.x < ENC_BLOCKS + PREP_BLOCKS) {
        int idx = (blockIdx.x - ENC_BLOCKS) * 128 + t;
        if (idx < 32 * OUTC) { g_mdec_WxQ[idx] = quad(mWx, OUTC, idx / OUTC, idx % OUTC); return; }
        idx -= 32 * OUTC;
        if (idx < 32 * NLOG) { g_mdec_WsQ[idx] = quad(mWs, NLOG, idx / NLOG, idx % NLOG); return; }
        return;
    }

    if (blockIdx.x >= ENC_BLOCKS + PREP_BLOCKS) {
        const int c = blockIdx.x - (ENC_BLOCKS + PREP_BLOCKS);  // 0..304
        const int isWs = (c >= OUTC);
        const int cc = isWs ? (c - OUTC) : c;
        const float* Wsrc = isWs ? decWs : decWx;
        const int cols = isWs ? NLOG : OUTC;

        __shared__ __align__(16) float col[EMBED];
        __shared__ float bred[128];

        col[t] = Wsrc[t * cols + cc];
        __syncthreads();

        const float4* row = (const float4*)(mencW2 + t * EMBED);
        const float4* c4 = (const float4*)col;
        float acc = 0.f;
#pragma unroll 8
        for (int q = 0; q < 32; q++) {
            float4 a = row[q], b = c4[q];
            acc += a.x * b.x + a.y * b.y + a.z * b.z + a.w * b.w;
        }
        float* dst = isWs ? (float*)g_decF_WsQ : (float*)g_decF_WxQ;
        dst[(((t >> 2) * cols) + cc) * 4 + (t & 3)] = acc;
        bred[t] = mencb2[t] * col[t];
        __syncthreads();
#pragma unroll
        for (int s = 64; s > 0; s >>= 1) {
            if (t < s) bred[t] += bred[t + s];
            __syncthreads();
        }
        if (t == 0) {
            if (isWs) g_bsF[cc] = bred[0] + decbs[cc];
            else      g_bxF[cc] = bred[0] + decbx[cc];
        }
        return;
    }

    // ---- obs encode, 4 agents/block ----
    const int a0 = blockIdx.x * 4;

    __shared__ __align__(16) float msg[4 * OBS_DEG][ORIG_P];
    __shared__ __align__(16) float S[4][EMBED];
    __shared__ float apos[4][2];

    if (t < 8) apos[t >> 1][t & 1] = agent_pos[(a0 + (t >> 1)) * 2 + (t & 1)];
    __syncthreads();

    for (int idx = t; idx < 4 * OBS_DEG * ORIG; idx += 128) {
        const int r = idx / ORIG;
        const int k = idx - r * ORIG;
        const int ag = r >> 3;
        const int e  = r & 7;
        const int o = obs_src[(a0 + ag) * OBS_DEG + e];
        float v;
        if (k < IN_DIM) v = obj_x[o * IN_DIM + k];
        else            v = obj_pos[o * POS_DIM + (k - IN_DIM)] - apos[ag][k - IN_DIM];
        msg[r][k] = v;
    }
    __syncthreads();

    ull w1p[9];
#pragma unroll
    for (int q = 0; q < 9; q++)
        w1p[q] = f2pack(W1[(2 * q) * EMBED + t], W1[(2 * q + 1) * EMBED + t]);
    const float b1t = b1[t];

#pragma unroll
    for (int ag = 0; ag < 4; ag++) {
        float acc = 0.f;
#pragma unroll
        for (int e = 0; e < OBS_DEG; e++) {
            const ulonglong2* r = (const ulonglong2*)msg[ag * OBS_DEG + e];
            ulonglong2 q0 = r[0], q1 = r[1], q2 = r[2], q3 = r[3];
            ull q4 = ((const ull*)msg[ag * OBS_DEG + e])[8];
            ull h = 0;
            h = f2fma(q0.x, w1p[0], h); h = f2fma(q0.y, w1p[1], h);
            h = f2fma(q1.x, w1p[2], h); h = f2fma(q1.y, w1p[3], h);
            h = f2fma(q2.x, w1p[4], h); h = f2fma(q2.y, w1p[5], h);
            h = f2fma(q3.x, w1p[6], h); h = f2fma(q3.y, w1p[7], h);
            h = f2fma(q4,   w1p[8], h);
            acc += fmaxf(f2sum(h) + b1t, 0.f);
        }
        S[ag][t] = acc;
    }
    __syncthreads();

    {
        ull ao[4];
#pragma unroll
        for (int ag = 0; ag < 4; ag++) ao[ag] = 0;
#pragma unroll 4
        for (int kq = 0; kq < 32; kq++) {
            const float w0 = eW2[(4 * kq    ) * EMBED + t];
            const float w1 = eW2[(4 * kq + 1) * EMBED + t];
            const float w2 = eW2[(4 * kq + 2) * EMBED + t];
            const float w3 = eW2[(4 * kq + 3) * EMBED + t];
            const ull wp0 = f2pack(w0, w1);
            const ull wp1 = f2pack(w2, w3);
#pragma unroll
            for (int ag = 0; ag < 4; ag++) {
                ulonglong2 z = *(const ulonglong2*)&S[ag][4 * kq];
                ao[ag] = f2fma(z.x, wp0, ao[ag]);
                ao[ag] = f2fma(z.y, wp1, ao[ag]);
            }
        }
        const float b2t = b2[t];
#pragma unroll
        for (int ag = 0; ag < 4; ag++)
            g_enc[(a0 + ag) * EMBED + t] = f2sum(ao[ag]) + b2t;
    }
}

// ---------------------------------------------------------------------------
// K2 (128 thr): per-SOURCE mdec decode, 8 agents/block.
// ---------------------------------------------------------------------------
__global__ __launch_bounds__(128) void mdec_kernel(
    const float* __restrict__ mdec_bs, const float* __restrict__ mdec_bx)
{
    const int j0 = blockIdx.x * 8;
    const int t = threadIdx.x;
    const int lane = t & 31;
    const int wrp  = t >> 5;

    __shared__ __align__(16) float zj[DEG][EMBED];
    __shared__ float psA[32][DEG], psB[32][DEG];
    __shared__ float logitsA[DEG][NLOG], logitsB[DEG][NLOG];

#pragma unroll
    for (int e = 0; e < DEG; e++) zj[e][t] = g_enc[(j0 + e) * EMBED + t];
    __syncthreads();

    {
        const ulonglong2* WQ = (const ulonglong2*)g_mdec_WxQ;
        ull acc0[DEG], acc1[DEG];
#pragma unroll
        for (int e = 0; e < DEG; e++) { acc0[e] = 0; acc1[e] = 0; }
#pragma unroll 4
        for (int kq = 0; kq < 32; kq++) {
            ulonglong2 w0 = WQ[kq * OUTC + t];
            ulonglong2 w1 = WQ[kq * OUTC + t + 128];
#pragma unroll
            for (int e = 0; e < DEG; e++) {
                ulonglong2 z = *(const ulonglong2*)&zj[e][4 * kq];
                acc0[e] = f2fma(z.x, w0.x, acc0[e]);
                acc0[e] = f2fma(z.y, w0.y, acc0[e]);
                acc1[e] = f2fma(z.x, w1.x, acc1[e]);
                acc1[e] = f2fma(z.y, w1.y, acc1[e]);
            }
        }
        const float bx0 = mdec_bx[t];
        const float bx1 = mdec_bx[t + 128];
#pragma unroll
        for (int e = 0; e < DEG; e++) {
            g_elems0[(j0 + e) * OUTC + t]       = f2sum(acc0[e]) + bx0;
            g_elems0[(j0 + e) * OUTC + t + 128] = f2sum(acc1[e]) + bx1;
        }
    }
    {
        const int kq0 = (wrp & 1) ? 16 : 0;
        if (wrp < 2) {
            const int c = 256 + lane;
            const ulonglong2* WQ = (const ulonglong2*)g_mdec_WxQ;
            ull acc[DEG];
#pragma unroll
            for (int e = 0; e < DEG; e++) acc[e] = 0;
#pragma unroll 4
            for (int kq = kq0; kq < kq0 + 16; kq++) {
                ulonglong2 w = WQ[kq * OUTC + c];
#pragma unroll
                for (int e = 0; e < DEG; e++) {
                    ulonglong2 z = *(const ulonglong2*)&zj[e][4 * kq];
                    acc[e] = f2fma(z.x, w.x, acc[e]);
                    acc[e] = f2fma(z.y, w.y, acc[e]);
                }
            }
            if (wrp == 0) {
#pragma unroll
                for (int e = 0; e < DEG; e++) psA[lane][e] = f2sum(acc[e]);
            } else {
#pragma unroll
                for (int e = 0; e < DEG; e++) psB[lane][e] = f2sum(acc[e]);
            }
        } else if (lane < NLOG) {
            const int s = lane;
            const ulonglong2* WsQ = (const ulonglong2*)g_mdec_WsQ;
            ull acc[DEG];
#pragma unroll
            for (int e = 0; e < DEG; e++) acc[e] = 0;
#pragma unroll 4
            for (int kq = kq0; kq < kq0 + 16; kq++) {
                ulonglong2 w = WsQ[kq * NLOG + s];
#pragma unroll
                for (int e = 0; e < DEG; e++) {
                    ulonglong2 z = *(const ulonglong2*)&zj[e][4 * kq];
                    acc[e] = f2fma(z.x, w.x, acc[e]);
                    acc[e] = f2fma(z.y, w.y, acc[e]);
                }
            }
            if (wrp == 2) {
                const float bs = mdec_bs[s];
#pragma unroll
                for (int e = 0; e < DEG; e++) logitsA[e][s] = f2sum(acc[e]) + bs;
            } else {
#pragma unroll
                for (int e = 0; e < DEG; e++) logitsB[e][s] = f2sum(acc[e]);
            }
        }
    }
    __syncthreads();

#pragma unroll
    for (int r = 0; r < 2; r++) {
        const int p = t + r * 128;
        const int cl = p >> 3;
        const int e  = p & 7;
        const int c  = 256 + cl;
        g_elems0[(j0 + e) * OUTC + c] = psA[cl][e] + psB[cl][e] + mdec_bx[c];
    }
    if (t < DEG) {
        float best = logitsA[t][0] + logitsB[t][0]; int bi = 0;
#pragma unroll
        for (int c = 1; c < NLOG; c++) {
            const float v = logitsA[t][c] + logitsB[t][c];
            if (v > best) { best = v; bi = c; }
        }
        g_npred[j0 + t] = bi;
    }
}

// ---------------------------------------------------------------------------
// K3 (128 thr): positions-first gather + dedup (float2, early-break) + cap +
// compact full-row gather + merge-encode -> g_Spre.
// ---------------------------------------------------------------------------
__global__ __launch_bounds__(128) void gather_kernel(
    const float* __restrict__ agent_pos,
    const float* __restrict__ menc_W1, const float* __restrict__ menc_b1,
    const int*   __restrict__ comm_src)
{
    const int i = blockIdx.x;
    const int t = threadIdx.x;
    const int lane = t & 31;
    const int wrp  = t >> 5;

    __shared__ __align__(16) float cand[MAX_OBJ][ORIG_P];
    __shared__ __align__(8)  float2 cpp[KTOT];
    __shared__ int   npred[DEG];
    __shared__ int   cidx[KTOT];
    __shared__ float relx[DEG], rely[DEG];
    __shared__ int   jidx[DEG];
    __shared__ int   kkeep[MAX_OBJ];
    __shared__ int   wtot[4], wtot2[4];
    __shared__ int   ncnts;

    if (t < DEG) {
        const int j = comm_src[i * DEG + t];
        jidx[t] = j;
        relx[t] = agent_pos[2 * j    ] - agent_pos[2 * i    ];
        rely[t] = agent_pos[2 * j + 1] - agent_pos[2 * i + 1];
        npred[t] = g_npred[j];
    }
    __syncthreads();

    // phase A: validity + positions only
    const int em = t >> 4, mm = t & 15;
    const int v0 = (mm < npred[em]) ? 1 : 0;
    float x0 = 0.f, y0 = 0.f;
    if (v0) {
        const float2 p = *(const float2*)&g_elems0[jidx[em] * OUTC + mm * ORIG + 16];
        x0 = p.x + relx[em];
        y0 = p.y + rely[em];
    }

    unsigned bm = __ballot_sync(0xffffffffu, v0);
    int pre = __popc(bm & ((1u << lane) - 1u));
    if (lane == 31) wtot[wrp] = pre + v0;
    __syncthreads();
    int off = 0;
#pragma unroll
    for (int q = 0; q < 4; q++) if (q < wrp) off += wtot[q];
    const int nv = wtot[0] + wtot[1] + wtot[2] + wtot[3];
    if (v0) { const int p = off + pre; cpp[p] = make_float2(x0, y0); cidx[p] = t; }
    __syncthreads();

    // phase B: dedup with early break
    int surv = 0;
    if (t < nv) {
        const float2 me = cpp[t];
        int dead = 0;
        for (int k = 0; k < t; k++) {
            const float2 o = cpp[k];
            const float dx = me.x - o.x;
            const float dy = me.y - o.y;
            if (fmaf(dx, dx, dy * dy) < THRES2) { dead = 1; break; }
        }
        surv = !dead;
    }

    // phase C: cap to 15
    unsigned bm2 = __ballot_sync(0xffffffffu, surv);
    int pre2 = __popc(bm2 & ((1u << lane) - 1u));
    if (lane == 31) wtot2[wrp] = pre2 + surv;
    __syncthreads();
    int off2 = 0;
#pragma unroll
    for (int q = 0; q < 4; q++) if (q < wrp) off2 += wtot2[q];
    const int tot2 = wtot2[0] + wtot2[1] + wtot2[2] + wtot2[3];
    const int rank = off2 + pre2;
    if (surv && rank < MAX_OBJ - 1) kkeep[rank] = cidx[t];
    if (t == 0) ncnts = (tot2 < MAX_OBJ - 1) ? tot2 : (MAX_OBJ - 1);
    __syncthreads();

    // phase D: compact full-row gather (<=15 rows)
    const int ncnt = ncnts;
    for (int idx = t; idx < ncnt * ORIG; idx += 128) {
        const int l = idx / ORIG;
        const int dim = idx - l * ORIG;
        const int li = kkeep[l];
        const int e = li >> 4, m = li & 15;
        float v = g_elems0[jidx[e] * OUTC + m * ORIG + dim];
        if (dim == 16) v += relx[e];
        if (dim == 17) v += rely[e];
        cand[l][dim] = v;
    }
    __syncthreads();

    // phase E: merge-encode
    {
        ull w1p[9];
#pragma unroll
        for (int q = 0; q < 9; q++)
            w1p[q] = f2pack(menc_W1[(2 * q) * EMBED + t], menc_W1[(2 * q + 1) * EMBED + t]);
        const float b1t = menc_b1[t];
        float acc = 0.f;
        for (int l = 0; l < ncnt; l++) {
            const ulonglong2* r = (const ulonglong2*)cand[l];
            ulonglong2 q0 = r[0], q1 = r[1], q2 = r[2], q3 = r[3];
            ull q4 = ((const ull*)cand[l])[8];
            ull h = 0;
            h = f2fma(q0.x, w1p[0], h); h = f2fma(q0.y, w1p[1], h);
            h = f2fma(q1.x, w1p[2], h); h = f2fma(q1.y, w1p[3], h);
            h = f2fma(q2.x, w1p[4], h); h = f2fma(q2.y, w1p[5], h);
            h = f2fma(q3.x, w1p[6], h); h = f2fma(q3.y, w1p[7], h);
            h = f2fma(q4,   w1p[8], h);
            acc += fmaxf(f2sum(h) + b1t, 0.f);
        }
        g_Spre[i * EMBED + t] = acc;
    }
}

// ---------------------------------------------------------------------------
// K4 (128 thr): COLUMN-SPLIT dec — grid 2048; block = (4 agents, half h).
// Half h computes output cols [144h, 144h+144); both halves compute logits
// (cheap) so each can mask its own writes. Half 0 writes batch/mask tails.
// ---------------------------------------------------------------------------
#define DAG 4
__global__ __launch_bounds__(128) void dec_kernel(
    float* __restrict__ out, int write_extra)
{
    const int i0 = (blockIdx.x >> 1) * DAG;
    const int h  = blockIdx.x & 1;
    const int cb = h * 144;             // column base
    const int t = threadIdx.x;
    const int lane = t & 31;
    const int wrp  = t >> 5;

    __shared__ __align__(16) float Sp[DAG][EMBED];
    __shared__ float dlog[DAG][NLOG];
    __shared__ int   n2s[DAG];

#pragma unroll
    for (int e = 0; e < DAG; e++) Sp[e][t] = g_Spre[(i0 + e) * EMBED + t];
    __syncthreads();

    // main: col cb+t (all threads) x 4 agents
    const int c0 = cb + t;
    ull a0[DAG];
#pragma unroll
    for (int e = 0; e < DAG; e++) a0[e] = 0;
    {
        const ulonglong2* WQ = (const ulonglong2*)g_decF_WxQ;
#pragma unroll 4
        for (int kq = 0; kq < 32; kq++) {
            ulonglong2 w = WQ[kq * OUTC + c0];
#pragma unroll
            for (int e = 0; e < DAG; e++) {
                ulonglong2 z = *(const ulonglong2*)&Sp[e][4 * kq];
                a0[e] = f2fma(z.x, w.x, a0[e]);
                a0[e] = f2fma(z.y, w.y, a0[e]);
            }
        }
    }
    // extra 16 cols: threads 0..15 -> col cb+128+t
    ull a1[DAG];
#pragma unroll
    for (int e = 0; e < DAG; e++) a1[e] = 0;
    const int c1 = cb + 128 + t;
    if (t < 16) {
        const ulonglong2* WQ = (const ulonglong2*)g_decF_WxQ;
#pragma unroll 4
        for (int kq = 0; kq < 32; kq++) {
            ulonglong2 w = WQ[kq * OUTC + c1];
#pragma unroll
            for (int e = 0; e < DAG; e++) {
                ulonglong2 z = *(const ulonglong2*)&Sp[e][4 * kq];
                a1[e] = f2fma(z.x, w.x, a1[e]);
                a1[e] = f2fma(z.y, w.y, a1[e]);
            }
        }
    }
    // logits (both halves compute; warp w -> agent w, lanes 0..16)
    if (lane < NLOG) {
        const ulonglong2* WsQ = (const ulonglong2*)g_decF_WsQ;
        ull al = 0;
#pragma unroll 4
        for (int kq = 0; kq < 32; kq++) {
            ulonglong2 w = WsQ[kq * NLOG + lane];
            ulonglong2 z = *(const ulonglong2*)&Sp[wrp][4 * kq];
            al = f2fma(z.x, w.x, al);
            al = f2fma(z.y, w.y, al);
        }
        dlog[wrp][lane] = f2sum(al) + g_bsF[lane];
    }
    __syncthreads();
    if (t < DAG) {
        float best = dlog[t][0]; int bi = 0;
#pragma unroll
        for (int c = 1; c < NLOG; c++) {
            if (dlog[t][c] > best) { best = dlog[t][c]; bi = c; }
        }
        n2s[t] = bi;
    }
    __syncthreads();

    // masked writes for this half's columns
    {
        const float bx0 = g_bxF[c0];
        const int m0 = c0 / ORIG;
#pragma unroll
        for (int e = 0; e < DAG; e++) {
            out[(size_t)(i0 + e) * OUTC + c0] = (m0 < n2s[e]) ? (f2sum(a0[e]) + bx0) : 0.f;
        }
        if (t < 16) {
            const float bx1 = g_bxF[c1];
            const int m1 = c1 / ORIG;
#pragma unroll
            for (int e = 0; e < DAG; e++) {
                out[(size_t)(i0 + e) * OUTC + c1] = (m1 < n2s[e]) ? (f2sum(a1[e]) + bx1) : 0.f;
            }
        }
    }

    // batch + mask tails: half 0 only (4 agents x 16 = 64 entries)
    if (h == 0 && write_extra && t < DAG * MAX_OBJ) {
        const int ag = t >> 4, m = t & 15;
        const size_t batch_off = (size_t)A_N * OUTC;
        const size_t mask_off  = batch_off + (size_t)A_N * MAX_OBJ;
        out[batch_off + (size_t)(i0 + ag) * MAX_OBJ + m] = (float)(i0 + ag);
        out[mask_off  + (size_t)(i0 + ag) * MAX_OBJ + m] = (m < n2s[ag]) ? 1.f : 0.f;
    }
}

extern "C" void kernel_launch(void* const* d_in, const int* in_sizes, int n_in,
                              void* d_out, int out_size) {
    const float* obj_x     = (const float*)d_in[0];
    const float* obj_pos   = (const float*)d_in[1];
    const float* agent_pos = (const float*)d_in[2];
    const float* enc_W1    = (const float*)d_in[3];
    const float* enc_b1    = (const float*)d_in[4];
    const float* enc_W2    = (const float*)d_in[5];
    const float* enc_b2    = (const float*)d_in[6];
    const float* mdec_Ws   = (const float*)d_in[7];
    const float* mdec_bs   = (const float*)d_in[8];
    const float* mdec_Wx   = (const float*)d_in[9];
    const float* mdec_bx   = (const float*)d_in[10];
    const float* menc_W1   = (const float*)d_in[11];
    const float* menc_b1   = (const float*)d_in[12];
    const float* menc_W2   = (const float*)d_in[13];
    const float* menc_b2   = (const float*)d_in[14];
    const float* dec_Ws    = (const float*)d_in[15];
    const float* dec_bs    = (const float*)d_in[16];
    const float* dec_Wx    = (const float*)d_in[17];
    const float* dec_bx    = (const float*)d_in[18];
    const int*   obs_ei    = (const int*)d_in[19];
    const int*   comm_ei   = (const int*)d_in[20];

    const int* obs_src  = obs_ei  + A_N * OBS_DEG;   // row 1
    const int* comm_src = comm_ei;                   // row 0

    pre_kernel<<<ENC_BLOCKS + PREP_BLOCKS + FOLD_BLOCKS, 128>>>(
        obj_x, obj_pos, agent_pos,
        enc_W1, enc_b1, enc_W2, enc_b2, obs_src,
        mdec_Wx, mdec_Ws,
        menc_W2, menc_b2, dec_Wx, dec_bx, dec_Ws, dec_bs);

    mdec_kernel<<<A_N / 8, 128>>>(mdec_bs, mdec_bx);

    gather_kernel<<<A_N, 128>>>(agent_pos, menc_W1, menc_b1, comm_src);

    const int full = A_N * OUTC + 2 * A_N * MAX_OBJ;
    const int write_extra = (out_size >= full) ? 1 : 0;

    dec_kernel<<<(A_N / DAG) * 2, 128>>>((float*)d_out, write_extra);
}

// round 16
// speedup vs baseline: 1.3767x; 1.3767x over previous
#include <cuda_runtime.h>
#include <cuda_bf16.h>

#define A_N      4096
#define N_OBJ    8192
#define IN_DIM   16
#define EMBED    128
#define MAX_OBJ  16
#define DEG      8
#define OBS_DEG  8
#define POS_DIM  2
#define ORIG     18          // IN_DIM + POS_DIM
#define ORIG_P   20          // padded row stride (80B, 16B aligned)
#define OUTC     288         // MAX_OBJ * ORIG
#define NLOG     17          // MAX_OBJ + 1
#define KTOT     128         // DEG * MAX_OBJ
#define THRES    0.02f
#define THRES2   (THRES * THRES)

typedef unsigned long long ull;

__device__ __forceinline__ ull f2fma(ull a, ull b, ull c) {
    ull d;
    asm("fma.rn.f32x2 %0, %1, %2, %3;" : "=l"(d) : "l"(a), "l"(b), "l"(c));
    return d;
}
__device__ __forceinline__ float f2sum(ull v) {
    float lo, hi;
    asm("mov.b64 {%0, %1}, %2;" : "=f"(lo), "=f"(hi) : "l"(v));
    return lo + hi;
}
__device__ __forceinline__ ull f2pack(float lo, float hi) {
    ull v;
    asm("mov.b64 %0, {%1, %2};" : "=l"(v) : "f"(lo), "f"(hi));
    return v;
}

// ---------------- device scratch ----------------
__device__ float  g_enc[A_N * EMBED];
__device__ float  g_elems0[A_N * OUTC];
__device__ int    g_npred[A_N];
__device__ float  g_Spre[A_N * EMBED];
// k-quad interleaved: Q[kq*cols + c] = {W[4kq][c], ..., W[4kq+3][c]}
__device__ float4 g_mdec_WxQ[32 * OUTC];
__device__ float4 g_mdec_WsQ[32 * NLOG];
// FOLDED dec weights: WxF = menc_W2 @ dec_Wx, WsF = menc_W2 @ dec_Ws
__device__ float4 g_decF_WxQ[32 * OUTC];
__device__ float4 g_decF_WsQ[32 * NLOG];
__device__ float  g_bxF[OUTC];
__device__ float  g_bsF[NLOG];

#define PREP_TOTAL (32 * OUTC + 32 * NLOG)
#define PREP_BLOCKS ((PREP_TOTAL + 127) / 128)
#define FOLD_BLOCKS (OUTC + NLOG)
#define ENC_BLOCKS (A_N / 4)

__device__ __forceinline__ float4 quad(const float* __restrict__ W, int cols, int kq, int c) {
    return make_float4(W[(4 * kq    ) * cols + c], W[(4 * kq + 1) * cols + c],
                       W[(4 * kq + 2) * cols + c], W[(4 * kq + 3) * cols + c]);
}

// ---------------------------------------------------------------------------
// K1 (fused, 128 thr): blocks [0,1024) = obs encode (raw enc_W2 — reads NO
// prep outputs); [1024,+PREP) = mdec quad prep; rest = dec weight fold.
// ---------------------------------------------------------------------------
__global__ __launch_bounds__(128) void pre_kernel(
    const float* __restrict__ obj_x, const float* __restrict__ obj_pos,
    const float* __restrict__ agent_pos,
    const float* __restrict__ W1, const float* __restrict__ b1,
    const float* __restrict__ eW2, const float* __restrict__ b2,
    const int*   __restrict__ obs_src,
    const float* __restrict__ mWx, const float* __restrict__ mWs,
    const float* __restrict__ mencW2, const float* __restrict__ mencb2,
    const float* __restrict__ decWx, const float* __restrict__ decbx,
    const float* __restrict__ decWs, const float* __restrict__ decbs)
{
    const int t = threadIdx.x;

    if (blockIdx.x >= ENC_BLOCKS && blockIdx.x < ENC_BLOCKS + PREP_BLOCKS) {
        int idx = (blockIdx.x - ENC_BLOCKS) * 128 + t;
        if (idx < 32 * OUTC) { g_mdec_WxQ[idx] = quad(mWx, OUTC, idx / OUTC, idx % OUTC); return; }
        idx -= 32 * OUTC;
        if (idx < 32 * NLOG) { g_mdec_WsQ[idx] = quad(mWs, NLOG, idx / NLOG, idx % NLOG); return; }
        return;
    }

    if (blockIdx.x >= ENC_BLOCKS + PREP_BLOCKS) {
        const int c = blockIdx.x - (ENC_BLOCKS + PREP_BLOCKS);  // 0..304
        const int isWs = (c >= OUTC);
        const int cc = isWs ? (c - OUTC) : c;
        const float* Wsrc = isWs ? decWs : decWx;
        const int cols = isWs ? NLOG : OUTC;

        __shared__ __align__(16) float col[EMBED];
        __shared__ float bred[128];

        col[t] = Wsrc[t * cols + cc];
        __syncthreads();

        const float4* row = (const float4*)(mencW2 + t * EMBED);
        const float4* c4 = (const float4*)col;
        float acc = 0.f;
#pragma unroll 8
        for (int q = 0; q < 32; q++) {
            float4 a = row[q], b = c4[q];
            acc += a.x * b.x + a.y * b.y + a.z * b.z + a.w * b.w;
        }
        float* dst = isWs ? (float*)g_decF_WsQ : (float*)g_decF_WxQ;
        dst[(((t >> 2) * cols) + cc) * 4 + (t & 3)] = acc;
        bred[t] = mencb2[t] * col[t];
        __syncthreads();
#pragma unroll
        for (int s = 64; s > 0; s >>= 1) {
            if (t < s) bred[t] += bred[t + s];
            __syncthreads();
        }
        if (t == 0) {
            if (isWs) g_bsF[cc] = bred[0] + decbs[cc];
            else      g_bxF[cc] = bred[0] + decbx[cc];
        }
        return;
    }

    // ---- obs encode, 4 agents/block ----
    const int a0 = blockIdx.x * 4;

    __shared__ __align__(16) float msg[4 * OBS_DEG][ORIG_P];
    __shared__ __align__(16) float S[4][EMBED];
    __shared__ float apos[4][2];

    if (t < 8) apos[t >> 1][t & 1] = agent_pos[(a0 + (t >> 1)) * 2 + (t & 1)];
    __syncthreads();

    for (int idx = t; idx < 4 * OBS_DEG * ORIG; idx += 128) {
        const int r = idx / ORIG;
        const int k = idx - r * ORIG;
        const int ag = r >> 3;
        const int e  = r & 7;
        const int o = obs_src[(a0 + ag) * OBS_DEG + e];
        float v;
        if (k < IN_DIM) v = obj_x[o * IN_DIM + k];
        else            v = obj_pos[o * POS_DIM + (k - IN_DIM)] - apos[ag][k - IN_DIM];
        msg[r][k] = v;
    }
    __syncthreads();

    ull w1p[9];
#pragma unroll
    for (int q = 0; q < 9; q++)
        w1p[q] = f2pack(W1[(2 * q) * EMBED + t], W1[(2 * q + 1) * EMBED + t]);
    const float b1t = b1[t];

#pragma unroll
    for (int ag = 0; ag < 4; ag++) {
        float acc = 0.f;
#pragma unroll
        for (int e = 0; e < OBS_DEG; e++) {
            const ulonglong2* r = (const ulonglong2*)msg[ag * OBS_DEG + e];
            ulonglong2 q0 = r[0], q1 = r[1], q2 = r[2], q3 = r[3];
            ull q4 = ((const ull*)msg[ag * OBS_DEG + e])[8];
            ull h = 0;
            h = f2fma(q0.x, w1p[0], h); h = f2fma(q0.y, w1p[1], h);
            h = f2fma(q1.x, w1p[2], h); h = f2fma(q1.y, w1p[3], h);
            h = f2fma(q2.x, w1p[4], h); h = f2fma(q2.y, w1p[5], h);
            h = f2fma(q3.x, w1p[6], h); h = f2fma(q3.y, w1p[7], h);
            h = f2fma(q4,   w1p[8], h);
            acc += fmaxf(f2sum(h) + b1t, 0.f);
        }
        S[ag][t] = acc;
    }
    __syncthreads();

    {
        ull ao[4];
#pragma unroll
        for (int ag = 0; ag < 4; ag++) ao[ag] = 0;
#pragma unroll 4
        for (int kq = 0; kq < 32; kq++) {
            const float w0 = eW2[(4 * kq    ) * EMBED + t];
            const float w1 = eW2[(4 * kq + 1) * EMBED + t];
            const float w2 = eW2[(4 * kq + 2) * EMBED + t];
            const float w3 = eW2[(4 * kq + 3) * EMBED + t];
            const ull wp0 = f2pack(w0, w1);
            const ull wp1 = f2pack(w2, w3);
#pragma unroll
            for (int ag = 0; ag < 4; ag++) {
                ulonglong2 z = *(const ulonglong2*)&S[ag][4 * kq];
                ao[ag] = f2fma(z.x, wp0, ao[ag]);
                ao[ag] = f2fma(z.y, wp1, ao[ag]);
            }
        }
        const float b2t = b2[t];
#pragma unroll
        for (int ag = 0; ag < 4; ag++)
            g_enc[(a0 + ag) * EMBED + t] = f2sum(ao[ag]) + b2t;
    }
}

// ---------------------------------------------------------------------------
// K2 (128 thr): per-SOURCE mdec decode, 8 agents/block.
// ---------------------------------------------------------------------------
__global__ __launch_bounds__(128) void mdec_kernel(
    const float* __restrict__ mdec_bs, const float* __restrict__ mdec_bx)
{
    const int j0 = blockIdx.x * 8;
    const int t = threadIdx.x;
    const int lane = t & 31;
    const int wrp  = t >> 5;

    __shared__ __align__(16) float zj[DEG][EMBED];
    __shared__ float psA[32][DEG], psB[32][DEG];
    __shared__ float logitsA[DEG][NLOG], logitsB[DEG][NLOG];

#pragma unroll
    for (int e = 0; e < DEG; e++) zj[e][t] = g_enc[(j0 + e) * EMBED + t];
    __syncthreads();

    {
        const ulonglong2* WQ = (const ulonglong2*)g_mdec_WxQ;
        ull acc0[DEG], acc1[DEG];
#pragma unroll
        for (int e = 0; e < DEG; e++) { acc0[e] = 0; acc1[e] = 0; }
#pragma unroll 4
        for (int kq = 0; kq < 32; kq++) {
            ulonglong2 w0 = WQ[kq * OUTC + t];
            ulonglong2 w1 = WQ[kq * OUTC + t + 128];
#pragma unroll
            for (int e = 0; e < DEG; e++) {
                ulonglong2 z = *(const ulonglong2*)&zj[e][4 * kq];
                acc0[e] = f2fma(z.x, w0.x, acc0[e]);
                acc0[e] = f2fma(z.y, w0.y, acc0[e]);
                acc1[e] = f2fma(z.x, w1.x, acc1[e]);
                acc1[e] = f2fma(z.y, w1.y, acc1[e]);
            }
        }
        const float bx0 = mdec_bx[t];
        const float bx1 = mdec_bx[t + 128];
#pragma unroll
        for (int e = 0; e < DEG; e++) {
            g_elems0[(j0 + e) * OUTC + t]       = f2sum(acc0[e]) + bx0;
            g_elems0[(j0 + e) * OUTC + t + 128] = f2sum(acc1[e]) + bx1;
        }
    }
    {
        const int kq0 = (wrp & 1) ? 16 : 0;
        if (wrp < 2) {
            const int c = 256 + lane;
            const ulonglong2* WQ = (const ulonglong2*)g_mdec_WxQ;
            ull acc[DEG];
#pragma unroll
            for (int e = 0; e < DEG; e++) acc[e] = 0;
#pragma unroll 4
            for (int kq = kq0; kq < kq0 + 16; kq++) {
                ulonglong2 w = WQ[kq * OUTC + c];
#pragma unroll
                for (int e = 0; e < DEG; e++) {
                    ulonglong2 z = *(const ulonglong2*)&zj[e][4 * kq];
                    acc[e] = f2fma(z.x, w.x, acc[e]);
                    acc[e] = f2fma(z.y, w.y, acc[e]);
                }
            }
            if (wrp == 0) {
#pragma unroll
                for (int e = 0; e < DEG; e++) psA[lane][e] = f2sum(acc[e]);
            } else {
#pragma unroll
                for (int e = 0; e < DEG; e++) psB[lane][e] = f2sum(acc[e]);
            }
        } else if (lane < NLOG) {
            const int s = lane;
            const ulonglong2* WsQ = (const ulonglong2*)g_mdec_WsQ;
            ull acc[DEG];
#pragma unroll
            for (int e = 0; e < DEG; e++) acc[e] = 0;
#pragma unroll 4
            for (int kq = kq0; kq < kq0 + 16; kq++) {
                ulonglong2 w = WsQ[kq * NLOG + s];
#pragma unroll
                for (int e = 0; e < DEG; e++) {
                    ulonglong2 z = *(const ulonglong2*)&zj[e][4 * kq];
                    acc[e] = f2fma(z.x, w.x, acc[e]);
                    acc[e] = f2fma(z.y, w.y, acc[e]);
                }
            }
            if (wrp == 2) {
                const float bs = mdec_bs[s];
#pragma unroll
                for (int e = 0; e < DEG; e++) logitsA[e][s] = f2sum(acc[e]) + bs;
            } else {
#pragma unroll
                for (int e = 0; e < DEG; e++) logitsB[e][s] = f2sum(acc[e]);
            }
        }
    }
    __syncthreads();

#pragma unroll
    for (int r = 0; r < 2; r++) {
        const int p = t + r * 128;
        const int cl = p >> 3;
        const int e  = p & 7;
        const int c  = 256 + cl;
        g_elems0[(j0 + e) * OUTC + c] = psA[cl][e] + psB[cl][e] + mdec_bx[c];
    }
    if (t < DEG) {
        float best = logitsA[t][0] + logitsB[t][0]; int bi = 0;
#pragma unroll
        for (int c = 1; c < NLOG; c++) {
            const float v = logitsA[t][c] + logitsB[t][c];
            if (v > best) { best = v; bi = c; }
        }
        g_npred[j0 + t] = bi;
    }
}

// ---------------------------------------------------------------------------
// K3 (128 thr): positions-first gather + dedup + cap + compact full-row
// gather + merge-encode -> g_Spre.   (exact R14 shape)
// ---------------------------------------------------------------------------
__global__ __launch_bounds__(128) void gather_kernel(
    const float* __restrict__ agent_pos,
    const float* __restrict__ menc_W1, const float* __restrict__ menc_b1,
    const int*   __restrict__ comm_src)
{
    const int i = blockIdx.x;
    const int t = threadIdx.x;
    const int lane = t & 31;
    const int wrp  = t >> 5;

    __shared__ __align__(16) float cand[MAX_OBJ][ORIG_P];
    __shared__ int   npred[DEG];
    __shared__ float cpx[KTOT], cpy[KTOT];
    __shared__ int   cidx[KTOT];
    __shared__ float relx[DEG], rely[DEG];
    __shared__ int   jidx[DEG];
    __shared__ int   kkeep[MAX_OBJ];
    __shared__ int   wtot[4], wtot2[4];
    __shared__ int   ncnts;

    if (t < DEG) {
        const int j = comm_src[i * DEG + t];
        jidx[t] = j;
        relx[t] = agent_pos[2 * j    ] - agent_pos[2 * i    ];
        rely[t] = agent_pos[2 * j + 1] - agent_pos[2 * i + 1];
        npred[t] = g_npred[j];
    }
    __syncthreads();

    // phase A: validity + positions only
    const int em = t >> 4, mm = t & 15;
    const int v0 = (mm < npred[em]) ? 1 : 0;
    float x0 = 0.f, y0 = 0.f;
    if (v0) {
        const float2 p = *(const float2*)&g_elems0[jidx[em] * OUTC + mm * ORIG + 16];
        x0 = p.x + relx[em];
        y0 = p.y + rely[em];
    }

    unsigned bm = __ballot_sync(0xffffffffu, v0);
    int pre = __popc(bm & ((1u << lane) - 1u));
    if (lane == 31) wtot[wrp] = pre + v0;
    __syncthreads();
    int off = 0;
#pragma unroll
    for (int q = 0; q < 4; q++) if (q < wrp) off += wtot[q];
    const int nv = wtot[0] + wtot[1] + wtot[2] + wtot[3];
    if (v0) { const int p = off + pre; cpx[p] = x0; cpy[p] = y0; cidx[p] = t; }
    __syncthreads();

    // phase B: dedup (squared threshold)
    int surv = 0;
    if (t < nv) {
        const float xx = cpx[t], yy = cpy[t];
        int dead = 0;
        for (int k = 0; k < t; k++) {
            const float dx = xx - cpx[k];
            const float dy = yy - cpy[k];
            if (fmaf(dx, dx, dy * dy) < THRES2) dead = 1;
        }
        surv = !dead;
    }

    // phase C: cap to 15
    unsigned bm2 = __ballot_sync(0xffffffffu, surv);
    int pre2 = __popc(bm2 & ((1u << lane) - 1u));
    if (lane == 31) wtot2[wrp] = pre2 + surv;
    __syncthreads();
    int off2 = 0;
#pragma unroll
    for (int q = 0; q < 4; q++) if (q < wrp) off2 += wtot2[q];
    const int tot2 = wtot2[0] + wtot2[1] + wtot2[2] + wtot2[3];
    const int rank = off2 + pre2;
    if (surv && rank < MAX_OBJ - 1) kkeep[rank] = cidx[t];
    if (t == 0) ncnts = (tot2 < MAX_OBJ - 1) ? tot2 : (MAX_OBJ - 1);
    __syncthreads();

    // phase D: compact full-row gather (<=15 rows)
    const int ncnt = ncnts;
    for (int idx = t; idx < ncnt * ORIG; idx += 128) {
        const int l = idx / ORIG;
        const int dim = idx - l * ORIG;
        const int li = kkeep[l];
        const int e = li >> 4, m = li & 15;
        float v = g_elems0[jidx[e] * OUTC + m * ORIG + dim];
        if (dim == 16) v += relx[e];
        if (dim == 17) v += rely[e];
        cand[l][dim] = v;
    }
    __syncthreads();

    // phase E: merge-encode
    {
        ull w1p[9];
#pragma unroll
        for (int q = 0; q < 9; q++)
            w1p[q] = f2pack(menc_W1[(2 * q) * EMBED + t], menc_W1[(2 * q + 1) * EMBED + t]);
        const float b1t = menc_b1[t];
        float acc = 0.f;
        for (int l = 0; l < ncnt; l++) {
            const ulonglong2* r = (const ulonglong2*)cand[l];
            ulonglong2 q0 = r[0], q1 = r[1], q2 = r[2], q3 = r[3];
            ull q4 = ((const ull*)cand[l])[8];
            ull h = 0;
            h = f2fma(q0.x, w1p[0], h); h = f2fma(q0.y, w1p[1], h);
            h = f2fma(q1.x, w1p[2], h); h = f2fma(q1.y, w1p[3], h);
            h = f2fma(q2.x, w1p[4], h); h = f2fma(q2.y, w1p[5], h);
            h = f2fma(q3.x, w1p[6], h); h = f2fma(q3.y, w1p[7], h);
            h = f2fma(q4,   w1p[8], h);
            acc += fmaxf(f2sum(h) + b1t, 0.f);
        }
        g_Spre[i * EMBED + t] = acc;
    }
}

// ---------------------------------------------------------------------------
// K4 (128 thr): 4 agents/block, folded GEMV, LOGITS-FIRST + column skip:
// all columns >= cmax = max(n2)*ORIG are masked for every agent, so the
// GEMV work for them is skipped entirely (whole warps drop out).
// ---------------------------------------------------------------------------
#define DAG 4
__global__ __launch_bounds__(128) void dec_kernel(
    float* __restrict__ out, int write_extra)
{
    const int i0 = blockIdx.x * DAG;
    const int t = threadIdx.x;
    const int lane = t & 31;
    const int wrp  = t >> 5;

    __shared__ __align__(16) float Sp[DAG][EMBED];
    __shared__ float dlog[DAG][NLOG];
    __shared__ int   n2s[DAG];

#pragma unroll
    for (int e = 0; e < DAG; e++) Sp[e][t] = g_Spre[(i0 + e) * EMBED + t];
    __syncthreads();

    // logits FIRST: warp w -> agent w, lanes 0..16
    if (lane < NLOG) {
        const ulonglong2* WsQ = (const ulonglong2*)g_decF_WsQ;
        ull al = 0;
#pragma unroll 4
        for (int kq = 0; kq < 32; kq++) {
            ulonglong2 w = WsQ[kq * NLOG + lane];
            ulonglong2 z = *(const ulonglong2*)&Sp[wrp][4 * kq];
            al = f2fma(z.x, w.x, al);
            al = f2fma(z.y, w.y, al);
        }
        dlog[wrp][lane] = f2sum(al) + g_bsF[lane];
    }
    __syncthreads();
    if (t < DAG) {
        float best = dlog[t][0]; int bi = 0;
#pragma unroll
        for (int c = 1; c < NLOG; c++) {
            if (dlog[t][c] > best) { best = dlog[t][c]; bi = c; }
        }
        n2s[t] = bi;
    }
    __syncthreads();

    const int n20 = n2s[0], n21 = n2s[1], n22 = n2s[2], n23 = n2s[3];
    int nmax = n20 > n21 ? n20 : n21;
    nmax = nmax > n22 ? nmax : n22;
    nmax = nmax > n23 ? nmax : n23;
    const int cmax = nmax * ORIG;       // columns >= cmax are zero for ALL 4 agents

    // main: cols {t, t+128} x 4 agents, skipping cols >= cmax
    ull a0[DAG], a1[DAG];
#pragma unroll
    for (int e = 0; e < DAG; e++) { a0[e] = 0; a1[e] = 0; }
    const bool do0 = (t < cmax);
    const bool do1 = (t + 128 < cmax);
    if (do1) {
        // both columns live
        const ulonglong2* WQ = (const ulonglong2*)g_decF_WxQ;
#pragma unroll 4
        for (int kq = 0; kq < 32; kq++) {
            ulonglong2 w0 = WQ[kq * OUTC + t];
            ulonglong2 w1 = WQ[kq * OUTC + t + 128];
#pragma unroll
            for (int e = 0; e < DAG; e++) {
                ulonglong2 z = *(const ulonglong2*)&Sp[e][4 * kq];
                a0[e] = f2fma(z.x, w0.x, a0[e]);
                a0[e] = f2fma(z.y, w0.y, a0[e]);
                a1[e] = f2fma(z.x, w1.x, a1[e]);
                a1[e] = f2fma(z.y, w1.y, a1[e]);
            }
        }
    } else if (do0) {
        const ulonglong2* WQ = (const ulonglong2*)g_decF_WxQ;
#pragma unroll 4
        for (int kq = 0; kq < 32; kq++) {
            ulonglong2 w0 = WQ[kq * OUTC + t];
#pragma unroll
            for (int e = 0; e < DAG; e++) {
                ulonglong2 z = *(const ulonglong2*)&Sp[e][4 * kq];
                a0[e] = f2fma(z.x, w0.x, a0[e]);
                a0[e] = f2fma(z.y, w0.y, a0[e]);
            }
        }
    }
    // tail: thread t -> agent t>>5, col 256+lane — only if cmax > 256
    ull at = 0;
    const int te = wrp;
    const int tc = 256 + lane;
    if (tc < cmax) {
        const ulonglong2* WQ = (const ulonglong2*)g_decF_WxQ;
#pragma unroll 4
        for (int kq = 0; kq < 32; kq++) {
            ulonglong2 w = WQ[kq * OUTC + tc];
            ulonglong2 z = *(const ulonglong2*)&Sp[te][4 * kq];
            at = f2fma(z.x, w.x, at);
            at = f2fma(z.y, w.y, at);
        }
    }

    // masked writes (skipped columns write exact 0)
    {
        const float bx0 = g_bxF[t];
        const float bx1 = g_bxF[t + 128];
        const int m0 = t / ORIG;
        const int m1 = (t + 128) / ORIG;
#pragma unroll
        for (int e = 0; e < DAG; e++) {
            const int n2 = n2s[e];
            out[(size_t)(i0 + e) * OUTC + t]       = (m0 < n2) ? (f2sum(a0[e]) + bx0) : 0.f;
            out[(size_t)(i0 + e) * OUTC + t + 128] = (m1 < n2) ? (f2sum(a1[e]) + bx1) : 0.f;
        }
        const int mt = tc / ORIG;
        out[(size_t)(i0 + te) * OUTC + tc] = (mt < n2s[te]) ? (f2sum(at) + g_bxF[tc]) : 0.f;
    }

    if (write_extra && t < DAG * MAX_OBJ) {
        const int ag = t >> 4, m = t & 15;
        const size_t batch_off = (size_t)A_N * OUTC;
        const size_t mask_off  = batch_off + (size_t)A_N * MAX_OBJ;
        out[batch_off + (size_t)(i0 + ag) * MAX_OBJ + m] = (float)(i0 + ag);
        out[mask_off  + (size_t)(i0 + ag) * MAX_OBJ + m] = (m < n2s[ag]) ? 1.f : 0.f;
    }
}

extern "C" void kernel_launch(void* const* d_in, const int* in_sizes, int n_in,
                              void* d_out, int out_size) {
    const float* obj_x     = (const float*)d_in[0];
    const float* obj_pos   = (const float*)d_in[1];
    const float* agent_pos = (const float*)d_in[2];
    const float* enc_W1    = (const float*)d_in[3];
    const float* enc_b1    = (const float*)d_in[4];
    const float* enc_W2    = (const float*)d_in[5];
    const float* enc_b2    = (const float*)d_in[6];
    const float* mdec_Ws   = (const float*)d_in[7];
    const float* mdec_bs   = (const float*)d_in[8];
    const float* mdec_Wx   = (const float*)d_in[9];
    const float* mdec_bx   = (const float*)d_in[10];
    const float* menc_W1   = (const float*)d_in[11];
    const float* menc_b1   = (const float*)d_in[12];
    const float* menc_W2   = (const float*)d_in[13];
    const float* menc_b2   = (const float*)d_in[14];
    const float* dec_Ws    = (const float*)d_in[15];
    const float* dec_bs    = (const float*)d_in[16];
    const float* dec_Wx    = (const float*)d_in[17];
    const float* dec_bx    = (const float*)d_in[18];
    const int*   obs_ei    = (const int*)d_in[19];
    const int*   comm_ei   = (const int*)d_in[20];

    const int* obs_src  = obs_ei  + A_N * OBS_DEG;   // row 1
    const int* comm_src = comm_ei;                   // row 0

    pre_kernel<<<ENC_BLOCKS + PREP_BLOCKS + FOLD_BLOCKS, 128>>>(
        obj_x, obj_pos, agent_pos,
        enc_W1, enc_b1, enc_W2, enc_b2, obs_src,
        mdec_Wx, mdec_Ws,
        menc_W2, menc_b2, dec_Wx, dec_bx, dec_Ws, dec_bs);

    mdec_kernel<<<A_N / 8, 128>>>(mdec_bs, mdec_bx);

    gather_kernel<<<A_N, 128>>>(agent_pos, menc_W1, menc_b1, comm_src);

    const int full = A_N * OUTC + 2 * A_N * MAX_OBJ;
    const int write_extra = (out_size >= full) ? 1 : 0;

    dec_kernel<<<A_N / DAG, 128>>>((float*)d_out, write_extra);
}